// round 13
// baseline (speedup 1.0000x reference)
#include <cuda_runtime.h>

#define Bn 4
#define Hh 512
#define Ww 512
#define HW (Hh*Ww)
#define Ntot (Bn*HW)
#define EPSf 1e-8f
#define NPAIR 10       // 20 iterations = 10 fused pairs
#define T2 28          // owned interior per block (after 2 iters), normal launches
#define T2L 27         // owned interior on the LAST launch (avg-fused output)
#define NT2 19         // ceil(512/28) == ceil(512/27) coverage with 19*27=513
#define SPU 33         // s_u pitch (float2)
#define SPP 33         // s_pa/s_pb pitch (float2)

// State in vector-packed device globals (no runtime alloc).
// pa=(p1x,p2x) read at w+-1 (horizontal), pb=(p1y,p2y) read at h+-1 (vertical).
__device__ float4 g_cfg[Ntot];        // (rho_c, gx, gy, pad)
__device__ float2 g_u2[2][Ntot];
__device__ float2 g_pa[2][Ntot];
__device__ float2 g_pb[2][Ntot];

// init state + cfg = (I1-I0, K_GRAD_x*I1, K_GRAD_y*I1), zero padding.
// Vectorized: each thread handles 4 consecutive pixels of one row.
__global__ void pre_kernel(const float* __restrict__ x) {
    int i = blockIdx.x*blockDim.x + threadIdx.x;
    if (i >= Ntot/4) return;
    int b   = i >> 16;               // HW/4 = 65536
    int hw4 = i & 65535;
    int h   = hw4 >> 7;              // 128 groups per row
    int wg  = (hw4 & 127) << 2;      // first col of the 4-pixel group

    const float* I0 = x + (size_t)b*2*HW;
    const float* I1 = I0 + HW;

    // rows h-1,h,h+1, cols wg-1 .. wg+4
    float r[3][6];
    #pragma unroll
    for (int d = 0; d < 3; d++) {
        int hh = h + d - 1;
        if ((unsigned)hh < Hh) {
            const float* row = I1 + hh*Ww;
            float4 m = *reinterpret_cast<const float4*>(row + wg);
            r[d][0] = (wg > 0) ? row[wg-1] : 0.f;
            r[d][1] = m.x; r[d][2] = m.y; r[d][3] = m.z; r[d][4] = m.w;
            r[d][5] = (wg+4 < Ww) ? row[wg+4] : 0.f;
        } else {
            #pragma unroll
            for (int j = 0; j < 6; j++) r[d][j] = 0.f;
        }
    }
    float4 c0 = *reinterpret_cast<const float4*>(I0 + h*Ww + wg);
    float i0c[4] = {c0.x, c0.y, c0.z, c0.w};

    int pidx = b*HW + h*Ww + wg;
    float2 z2 = make_float2(0.f, 0.f);
    float4 z4 = make_float4(0.f, 0.f, 0.f, 0.f);
    #pragma unroll
    for (int k = 0; k < 4; k++) {
        float gx = (-r[0][k] + r[0][k+2] - 2.f*r[1][k] + 2.f*r[1][k+2]
                    - r[2][k] + r[2][k+2]) * (1.f/6.f);
        float gy = (-r[0][k] - 2.f*r[0][k+1] - r[0][k+2]
                    + r[2][k] + 2.f*r[2][k+1] + r[2][k+2]) * (1.f/6.f);
        g_cfg[pidx+k] = make_float4(r[1][k+1] - i0c[k], gx, gy, 0.f);
        g_u2[0][pidx+k] = z2;
    }
    *reinterpret_cast<float4*>(&g_pa[0][pidx])   = z4;
    *reinterpret_cast<float4*>(&g_pa[0][pidx+2]) = z4;
    *reinterpret_cast<float4*>(&g_pb[0][pidx])   = z4;
    *reinterpret_cast<float4*>(&g_pb[0][pidx+2]) = z4;
}

// TWO fused TV-L1 iterations per launch (exact R5 structure, natural regs).
//   A: u(1) on 32x32    B: p(1) on 31x31    C: u(2) on [1,30)^2
//   D (normal): p(2)+state writes on [1,29)^2 (28x28 owned)
//   D (last):   fused AvgPool3x3 of u(2) from SMEM on [2,29)^2 (27x27 owned),
//               written straight to `out`; no state writes (nothing reads them).
// Out-of-range/out-of-image values are 0 => exact zero-pad semantics
// (phase C zeroes out-of-image points, so the 9-tap sum sees true zero-pad).
__global__ __launch_bounds__(256) void iter2_kernel(int src, int last,
    float* __restrict__ out,
    const float* __restrict__ lam_p, const float* __restrict__ tau_p,
    const float* __restrict__ theta_p,
    const float* __restrict__ wx, const float* __restrict__ wy)
{
    const float theta = theta_p[0];
    const float tl = theta * lam_p[0];
    const float rr = tau_p[0] / theta;
    const float wx0 = wx[0], wx1 = wx[1], wx2 = wx[2];
    const float wy0 = wy[0], wy1 = wy[1], wy2 = wy[2];

    const float2* __restrict__ u_in  = g_u2[src];
    const float2* __restrict__ pa_in = g_pa[src];
    const float2* __restrict__ pb_in = g_pb[src];
    float2* __restrict__ u_out  = g_u2[src^1];
    float2* __restrict__ pa_out = g_pa[src^1];
    float2* __restrict__ pb_out = g_pb[src^1];

    const int lc = threadIdx.x & 31;
    const int ty = threadIdx.x >> 5;
    const int b  = blockIdx.z;
    const int gh0 = last ? (blockIdx.y * T2L - 2) : (blockIdx.y * T2 - 1);
    const int gw0 = last ? (blockIdx.x * T2L - 2) : (blockIdx.x * T2 - 1);
    const int gw  = gw0 + lc;
    const int base = b * HW;
    const bool wok = (unsigned)gw < Ww;

    __shared__ float2 s_u [32*SPU];
    __shared__ float2 s_pa[31*SPP];
    __shared__ float2 s_pb[31*SPP];

    // ---- Phase A: u(1) on full 32x32 region ----
    #pragma unroll
    for (int i = 0; i < 4; i++) {
        int lr = ty + i*8;
        int gh = gh0 + lr;
        float2 res = make_float2(0.f, 0.f);
        if ((unsigned)gh < Hh && wok) {
            int idx = base + gh*Ww + gw;
            float4 cfg = g_cfg[idx];
            float2 u  = u_in[idx];
            float2 pa = pa_in[idx];
            float2 pb = pb_in[idx];
            float2 z2 = make_float2(0.f, 0.f);
            float2 pl = (gw > 0)    ? pa_in[idx-1]  : z2;
            float2 pr = (gw < Ww-1) ? pa_in[idx+1]  : z2;
            float2 pu = (gh > 0)    ? pb_in[idx-Ww] : z2;
            float2 pd = (gh < Hh-1) ? pb_in[idx+Ww] : z2;
            float gx = cfg.y, gy = cfg.z;
            float rho = cfg.x + gx*u.x + gy*u.y;
            float ng = gx*gx + gy*gy + EPSf;
            float th = tl * ng;
            float d0, d1;
            if (fabsf(rho) < th) {
                float inv = 1.0f / ng;
                d0 = rho*gx*inv; d1 = rho*gy*inv;
            } else {
                float s = (rho > 0.f) ? 1.f : ((rho < 0.f) ? -1.f : 0.f);
                d0 = tl*gx*s; d1 = tl*gy*s;
            }
            float div1 = wx0*pl.x + wx1*pa.x + wx2*pr.x + wy0*pu.x + wy1*pb.x + wy2*pd.x;
            float div2 = wx0*pl.y + wx1*pa.y + wx2*pr.y + wy0*pu.y + wy1*pb.y + wy2*pd.y;
            res.x = (u.x - d0) + theta*div1;
            res.y = (u.y - d1) + theta*div2;
        }
        s_u[lr*SPU + lc] = res;
    }
    __syncthreads();

    // ---- Phase B: p(1) on 31x31 region ----
    #pragma unroll
    for (int i = 0; i < 4; i++) {
        int lr = ty + i*8;
        if (lr < 31 && lc < 31) {
            int gh = gh0 + lr;
            float2 ra = make_float2(0.f, 0.f), rb = make_float2(0.f, 0.f);
            if ((unsigned)gh < Hh && wok) {
                int idx = base + gh*Ww + gw;
                float2 pa = pa_in[idx];
                float2 pb = pb_in[idx];
                float2 c   = s_u[lr*SPU + lc];
                float2 rgt = s_u[lr*SPU + lc + 1];
                float2 dwn = s_u[(lr+1)*SPU + lc];
                float gx0 = rgt.x - c.x, gy0 = dwn.x - c.x;
                float gx1 = rgt.y - c.y, gy1 = dwn.y - c.y;
                float i1 = 1.f / (1.f + rr*(fabsf(gx0) + fabsf(gy0)));
                float i2 = 1.f / (1.f + rr*(fabsf(gx1) + fabsf(gy1)));
                ra = make_float2((pa.x + rr*gx0)*i1, (pa.y + rr*gx1)*i2);
                rb = make_float2((pb.x + rr*gy0)*i1, (pb.y + rr*gy1)*i2);
            }
            s_pa[lr*SPP + lc] = ra;
            s_pb[lr*SPP + lc] = rb;
        }
    }
    __syncthreads();

    // ---- Phase C: u(2) on [1,30)^2; SMEM only; overwrite s_u in place ----
    #pragma unroll
    for (int i = 0; i < 4; i++) {
        int lr = ty + i*8;
        if (lr >= 1 && lr < 30 && lc >= 1 && lc < 30) {
            int gh = gh0 + lr;
            float2 res = make_float2(0.f, 0.f);
            if ((unsigned)gh < Hh && wok) {
                int idx = base + gh*Ww + gw;
                float4 cfg = g_cfg[idx];
                float2 u  = s_u[lr*SPU + lc];
                float2 pa = s_pa[lr*SPP + lc];
                float2 pb = s_pb[lr*SPP + lc];
                float2 pl = s_pa[lr*SPP + lc - 1];
                float2 pr = s_pa[lr*SPP + lc + 1];
                float2 pu = s_pb[(lr-1)*SPP + lc];
                float2 pd = s_pb[(lr+1)*SPP + lc];
                float gx = cfg.y, gy = cfg.z;
                float rho = cfg.x + gx*u.x + gy*u.y;
                float ng = gx*gx + gy*gy + EPSf;
                float th = tl * ng;
                float d0, d1;
                if (fabsf(rho) < th) {
                    float inv = 1.0f / ng;
                    d0 = rho*gx*inv; d1 = rho*gy*inv;
                } else {
                    float s = (rho > 0.f) ? 1.f : ((rho < 0.f) ? -1.f : 0.f);
                    d0 = tl*gx*s; d1 = tl*gy*s;
                }
                float div1 = wx0*pl.x + wx1*pa.x + wx2*pr.x + wy0*pu.x + wy1*pb.x + wy2*pd.x;
                float div2 = wx0*pl.y + wx1*pa.y + wx2*pr.y + wy0*pu.y + wy1*pb.y + wy2*pd.y;
                res.x = (u.x - d0) + theta*div1;
                res.y = (u.y - d1) + theta*div2;
            }
            s_u[lr*SPU + lc] = res;
        }
    }
    __syncthreads();

    if (!last) {
        // ---- Phase D: p(2) + state writes on the 28x28 owned interior ----
        #pragma unroll
        for (int i = 0; i < 4; i++) {
            int lr = ty + i*8;
            if (lr >= 1 && lr < 29 && lc >= 1 && lc < 29) {
                int gh = gh0 + lr;
                if ((unsigned)gh < Hh && wok) {
                    int idx = base + gh*Ww + gw;
                    float2 c = s_u[lr*SPU + lc];
                    u_out[idx] = c;
                    float2 pa  = s_pa[lr*SPP + lc];
                    float2 pb  = s_pb[lr*SPP + lc];
                    float2 rgt = s_u[lr*SPU + lc + 1];
                    float2 dwn = s_u[(lr+1)*SPU + lc];
                    float gx0 = rgt.x - c.x, gy0 = dwn.x - c.x;
                    float gx1 = rgt.y - c.y, gy1 = dwn.y - c.y;
                    float i1 = 1.f / (1.f + rr*(fabsf(gx0) + fabsf(gy0)));
                    float i2 = 1.f / (1.f + rr*(fabsf(gx1) + fabsf(gy1)));
                    pa_out[idx] = make_float2((pa.x + rr*gx0)*i1, (pa.y + rr*gx1)*i2);
                    pb_out[idx] = make_float2((pb.x + rr*gy0)*i1, (pb.y + rr*gy1)*i2);
                }
            }
        }
    } else {
        // ---- Phase D (last): AvgPool3x3(u(2))/9 on [2,29)^2, direct to out ----
        #pragma unroll
        for (int i = 0; i < 4; i++) {
            int lr = ty + i*8;
            if (lr >= 2 && lr < 29 && lc >= 2 && lc < 29) {
                int gh = gh0 + lr;
                if ((unsigned)gh < Hh && wok) {
                    float sx = 0.f, sy = 0.f;
                    #pragma unroll
                    for (int dr = -1; dr <= 1; dr++) {
                        #pragma unroll
                        for (int dc = -1; dc <= 1; dc++) {
                            float2 v = s_u[(lr+dr)*SPU + (lc+dc)];
                            sx += v.x; sy += v.y;
                        }
                    }
                    int o = b*2*HW + gh*Ww + gw;
                    out[o]      = sx * (1.f/9.f);
                    out[o + HW] = sy * (1.f/9.f);
                }
            }
        }
    }
}

extern "C" void kernel_launch(void* const* d_in, const int* in_sizes, int n_in,
                              void* d_out, int out_size) {
    const float* x     = (const float*)d_in[0];
    const float* lam   = (const float*)d_in[1];
    const float* tau   = (const float*)d_in[2];
    const float* theta = (const float*)d_in[3];
    const float* wx    = (const float*)d_in[4];
    const float* wy    = (const float*)d_in[5];
    float* out = (float*)d_out;

    pre_kernel<<<(Ntot/4 + 255)/256, 256>>>(x);

    dim3 grid(NT2, NT2, Bn);   // 19 x 19 x 4 = 1444 blocks (both tilings covered)
    for (int i = 0; i < NPAIR; i++)
        iter2_kernel<<<grid, 256>>>(i & 1, i == NPAIR-1, out, lam, tau, theta, wx, wy);
}

// round 15
// speedup vs baseline: 1.0185x; 1.0185x over previous
#include <cuda_runtime.h>

#define Bn 4
#define Hh 512
#define Ww 512
#define HW (Hh*Ww)
#define Ntot (Bn*HW)
#define EPSf 1e-8f
#define NPAIR 10       // 20 iterations = 10 fused pairs
#define T2 28          // owned interior per block (after 2 iters)
#define NT2 19         // ceil(512/28)
#define SPU 33         // s_u pitch (float2)
#define SPP 33         // s_pa/s_pb pitch (float2)

// State in vector-packed device globals (no runtime alloc).
// pa=(p1x,p2x) read at w+-1 (horizontal), pb=(p1y,p2y) read at h+-1 (vertical).
__device__ float4 g_cfg[Ntot];        // (rho_c, gx, gy, pad)
__device__ float2 g_u2[2][Ntot];
__device__ float2 g_pa[2][Ntot];
__device__ float2 g_pb[2][Ntot];

// init state + cfg = (I1-I0, K_GRAD_x*I1, K_GRAD_y*I1), zero padding.
// Vectorized: each thread handles 4 consecutive pixels of one row.
__global__ void pre_kernel(const float* __restrict__ x) {
    int i = blockIdx.x*blockDim.x + threadIdx.x;
    if (i >= Ntot/4) return;
    int b   = i >> 16;               // HW/4 = 65536
    int hw4 = i & 65535;
    int h   = hw4 >> 7;              // 128 groups per row
    int wg  = (hw4 & 127) << 2;      // first col of the 4-pixel group

    const float* I0 = x + (size_t)b*2*HW;
    const float* I1 = I0 + HW;

    // rows h-1,h,h+1, cols wg-1 .. wg+4
    float r[3][6];
    #pragma unroll
    for (int d = 0; d < 3; d++) {
        int hh = h + d - 1;
        if ((unsigned)hh < Hh) {
            const float* row = I1 + hh*Ww;
            float4 m = *reinterpret_cast<const float4*>(row + wg);
            r[d][0] = (wg > 0) ? row[wg-1] : 0.f;
            r[d][1] = m.x; r[d][2] = m.y; r[d][3] = m.z; r[d][4] = m.w;
            r[d][5] = (wg+4 < Ww) ? row[wg+4] : 0.f;
        } else {
            #pragma unroll
            for (int j = 0; j < 6; j++) r[d][j] = 0.f;
        }
    }
    float4 c0 = *reinterpret_cast<const float4*>(I0 + h*Ww + wg);
    float i0c[4] = {c0.x, c0.y, c0.z, c0.w};

    int pidx = b*HW + h*Ww + wg;
    float2 z2 = make_float2(0.f, 0.f);
    float4 z4 = make_float4(0.f, 0.f, 0.f, 0.f);
    #pragma unroll
    for (int k = 0; k < 4; k++) {
        float gx = (-r[0][k] + r[0][k+2] - 2.f*r[1][k] + 2.f*r[1][k+2]
                    - r[2][k] + r[2][k+2]) * (1.f/6.f);
        float gy = (-r[0][k] - 2.f*r[0][k+1] - r[0][k+2]
                    + r[2][k] + 2.f*r[2][k+1] + r[2][k+2]) * (1.f/6.f);
        g_cfg[pidx+k] = make_float4(r[1][k+1] - i0c[k], gx, gy, 0.f);
        g_u2[0][pidx+k] = z2;
    }
    *reinterpret_cast<float4*>(&g_pa[0][pidx])   = z4;
    *reinterpret_cast<float4*>(&g_pa[0][pidx+2]) = z4;
    *reinterpret_cast<float4*>(&g_pb[0][pidx])   = z4;
    *reinterpret_cast<float4*>(&g_pb[0][pidx+2]) = z4;
}

// TWO fused TV-L1 iterations per launch — byte-exact R5 kernel (the proven
// optimum: natural regs=45, SMEM for cross-thread values, L1-hit reloads,
// no cross-phase register arrays, uniform tiling every launch).
//   A: u(1) on 32x32    B: p(1) on 31x31
//   C: u(2) on [1,30)^2 D: p(2)+writes on [1,29)^2 (28x28 owned interior)
// Out-of-range/out-of-image values are 0 => exact zero-pad semantics.
__global__ __launch_bounds__(256) void iter2_kernel(int src, int last,
    const float* __restrict__ lam_p, const float* __restrict__ tau_p,
    const float* __restrict__ theta_p,
    const float* __restrict__ wx, const float* __restrict__ wy)
{
    const float theta = theta_p[0];
    const float tl = theta * lam_p[0];
    const float rr = tau_p[0] / theta;
    const float wx0 = wx[0], wx1 = wx[1], wx2 = wx[2];
    const float wy0 = wy[0], wy1 = wy[1], wy2 = wy[2];

    const float2* __restrict__ u_in  = g_u2[src];
    const float2* __restrict__ pa_in = g_pa[src];
    const float2* __restrict__ pb_in = g_pb[src];
    float2* __restrict__ u_out  = g_u2[src^1];
    float2* __restrict__ pa_out = g_pa[src^1];
    float2* __restrict__ pb_out = g_pb[src^1];

    const int lc = threadIdx.x & 31;
    const int ty = threadIdx.x >> 5;
    const int b  = blockIdx.z;
    const int gh0 = blockIdx.y * T2 - 1;
    const int gw0 = blockIdx.x * T2 - 1;
    const int gw  = gw0 + lc;
    const int base = b * HW;
    const bool wok = (unsigned)gw < Ww;

    __shared__ float2 s_u [32*SPU];
    __shared__ float2 s_pa[31*SPP];
    __shared__ float2 s_pb[31*SPP];

    // ---- Phase A: u(1) on full 32x32 region ----
    #pragma unroll
    for (int i = 0; i < 4; i++) {
        int lr = ty + i*8;
        int gh = gh0 + lr;
        float2 res = make_float2(0.f, 0.f);
        if ((unsigned)gh < Hh && wok) {
            int idx = base + gh*Ww + gw;
            float4 cfg = g_cfg[idx];
            float2 u  = u_in[idx];
            float2 pa = pa_in[idx];
            float2 pb = pb_in[idx];
            float2 z2 = make_float2(0.f, 0.f);
            float2 pl = (gw > 0)    ? pa_in[idx-1]  : z2;
            float2 pr = (gw < Ww-1) ? pa_in[idx+1]  : z2;
            float2 pu = (gh > 0)    ? pb_in[idx-Ww] : z2;
            float2 pd = (gh < Hh-1) ? pb_in[idx+Ww] : z2;
            float gx = cfg.y, gy = cfg.z;
            float rho = cfg.x + gx*u.x + gy*u.y;
            float ng = gx*gx + gy*gy + EPSf;
            float th = tl * ng;
            float d0, d1;
            if (fabsf(rho) < th) {
                float inv = 1.0f / ng;
                d0 = rho*gx*inv; d1 = rho*gy*inv;
            } else {
                float s = (rho > 0.f) ? 1.f : ((rho < 0.f) ? -1.f : 0.f);
                d0 = tl*gx*s; d1 = tl*gy*s;
            }
            float div1 = wx0*pl.x + wx1*pa.x + wx2*pr.x + wy0*pu.x + wy1*pb.x + wy2*pd.x;
            float div2 = wx0*pl.y + wx1*pa.y + wx2*pr.y + wy0*pu.y + wy1*pb.y + wy2*pd.y;
            res.x = (u.x - d0) + theta*div1;
            res.y = (u.y - d1) + theta*div2;
        }
        s_u[lr*SPU + lc] = res;
    }
    __syncthreads();

    // ---- Phase B: p(1) on 31x31 region ----
    #pragma unroll
    for (int i = 0; i < 4; i++) {
        int lr = ty + i*8;
        if (lr < 31 && lc < 31) {
            int gh = gh0 + lr;
            float2 ra = make_float2(0.f, 0.f), rb = make_float2(0.f, 0.f);
            if ((unsigned)gh < Hh && wok) {
                int idx = base + gh*Ww + gw;
                float2 pa = pa_in[idx];
                float2 pb = pb_in[idx];
                float2 c   = s_u[lr*SPU + lc];
                float2 rgt = s_u[lr*SPU + lc + 1];
                float2 dwn = s_u[(lr+1)*SPU + lc];
                float gx0 = rgt.x - c.x, gy0 = dwn.x - c.x;
                float gx1 = rgt.y - c.y, gy1 = dwn.y - c.y;
                float i1 = 1.f / (1.f + rr*(fabsf(gx0) + fabsf(gy0)));
                float i2 = 1.f / (1.f + rr*(fabsf(gx1) + fabsf(gy1)));
                ra = make_float2((pa.x + rr*gx0)*i1, (pa.y + rr*gx1)*i2);
                rb = make_float2((pb.x + rr*gy0)*i1, (pb.y + rr*gy1)*i2);
            }
            s_pa[lr*SPP + lc] = ra;
            s_pb[lr*SPP + lc] = rb;
        }
    }
    __syncthreads();

    // ---- Phase C: u(2) on [1,30)^2; SMEM only; overwrite s_u in place ----
    #pragma unroll
    for (int i = 0; i < 4; i++) {
        int lr = ty + i*8;
        if (lr >= 1 && lr < 30 && lc >= 1 && lc < 30) {
            int gh = gh0 + lr;
            float2 res = make_float2(0.f, 0.f);
            if ((unsigned)gh < Hh && wok) {
                int idx = base + gh*Ww + gw;
                float4 cfg = g_cfg[idx];
                float2 u  = s_u[lr*SPU + lc];
                float2 pa = s_pa[lr*SPP + lc];
                float2 pb = s_pb[lr*SPP + lc];
                float2 pl = s_pa[lr*SPP + lc - 1];
                float2 pr = s_pa[lr*SPP + lc + 1];
                float2 pu = s_pb[(lr-1)*SPP + lc];
                float2 pd = s_pb[(lr+1)*SPP + lc];
                float gx = cfg.y, gy = cfg.z;
                float rho = cfg.x + gx*u.x + gy*u.y;
                float ng = gx*gx + gy*gy + EPSf;
                float th = tl * ng;
                float d0, d1;
                if (fabsf(rho) < th) {
                    float inv = 1.0f / ng;
                    d0 = rho*gx*inv; d1 = rho*gy*inv;
                } else {
                    float s = (rho > 0.f) ? 1.f : ((rho < 0.f) ? -1.f : 0.f);
                    d0 = tl*gx*s; d1 = tl*gy*s;
                }
                float div1 = wx0*pl.x + wx1*pa.x + wx2*pr.x + wy0*pu.x + wy1*pb.x + wy2*pd.x;
                float div2 = wx0*pl.y + wx1*pa.y + wx2*pr.y + wy0*pu.y + wy1*pb.y + wy2*pd.y;
                res.x = (u.x - d0) + theta*div1;
                res.y = (u.y - d1) + theta*div2;
            }
            s_u[lr*SPU + lc] = res;
        }
    }
    __syncthreads();

    // ---- Phase D: p(2) + global writes on the 28x28 owned interior ----
    #pragma unroll
    for (int i = 0; i < 4; i++) {
        int lr = ty + i*8;
        if (lr >= 1 && lr < 29 && lc >= 1 && lc < 29) {
            int gh = gh0 + lr;
            if ((unsigned)gh < Hh && wok) {
                int idx = base + gh*Ww + gw;
                float2 c = s_u[lr*SPU + lc];
                u_out[idx] = c;
                if (!last) {
                    float2 pa  = s_pa[lr*SPP + lc];
                    float2 pb  = s_pb[lr*SPP + lc];
                    float2 rgt = s_u[lr*SPU + lc + 1];
                    float2 dwn = s_u[(lr+1)*SPU + lc];
                    float gx0 = rgt.x - c.x, gy0 = dwn.x - c.x;
                    float gx1 = rgt.y - c.y, gy1 = dwn.y - c.y;
                    float i1 = 1.f / (1.f + rr*(fabsf(gx0) + fabsf(gy0)));
                    float i2 = 1.f / (1.f + rr*(fabsf(gx1) + fabsf(gy1)));
                    pa_out[idx] = make_float2((pa.x + rr*gx0)*i1, (pa.y + rr*gx1)*i2);
                    pb_out[idx] = make_float2((pb.x + rr*gy0)*i1, (pb.y + rr*gy1)*i2);
                }
            }
        }
    }
}

// AvgPool2d(3, stride 1, pad 1, count_include_pad -> always /9), both channels.
// Vectorized: 4 consecutive pixels per thread, column-sum reuse, float4 stores.
__global__ void avg_kernel(float* __restrict__ out) {
    int i = blockIdx.x*blockDim.x + threadIdx.x;
    if (i >= Ntot/4) return;
    int b   = i >> 16;
    int hw4 = i & 65535;
    int h   = hw4 >> 7;
    int wg  = (hw4 & 127) << 2;
    const float2* u = g_u2[0] + b*HW;   // final state is in buf 0 after 10 pairs

    float2 cs[6];
    #pragma unroll
    for (int j = 0; j < 6; j++) cs[j] = make_float2(0.f, 0.f);
    #pragma unroll
    for (int d = 0; d < 3; d++) {
        int hh = h + d - 1;
        if ((unsigned)hh >= Hh) continue;
        const float2* row = u + hh*Ww;
        float4 m0 = *reinterpret_cast<const float4*>(row + wg);      // px wg, wg+1
        float4 m1 = *reinterpret_cast<const float4*>(row + wg + 2);  // px wg+2, wg+3
        if (wg > 0)      { float2 t = row[wg-1]; cs[0].x += t.x; cs[0].y += t.y; }
        cs[1].x += m0.x; cs[1].y += m0.y;
        cs[2].x += m0.z; cs[2].y += m0.w;
        cs[3].x += m1.x; cs[3].y += m1.y;
        cs[4].x += m1.z; cs[4].y += m1.w;
        if (wg+4 < Ww)   { float2 t = row[wg+4]; cs[5].x += t.x; cs[5].y += t.y; }
    }
    float4 ox, oy;
    ox.x = (cs[0].x + cs[1].x + cs[2].x) * (1.f/9.f);
    ox.y = (cs[1].x + cs[2].x + cs[3].x) * (1.f/9.f);
    ox.z = (cs[2].x + cs[3].x + cs[4].x) * (1.f/9.f);
    ox.w = (cs[3].x + cs[4].x + cs[5].x) * (1.f/9.f);
    oy.x = (cs[0].y + cs[1].y + cs[2].y) * (1.f/9.f);
    oy.y = (cs[1].y + cs[2].y + cs[3].y) * (1.f/9.f);
    oy.z = (cs[2].y + cs[3].y + cs[4].y) * (1.f/9.f);
    oy.w = (cs[3].y + cs[4].y + cs[5].y) * (1.f/9.f);
    int o = b*2*HW + h*Ww + wg;
    *reinterpret_cast<float4*>(out + o)      = ox;
    *reinterpret_cast<float4*>(out + o + HW) = oy;
}

extern "C" void kernel_launch(void* const* d_in, const int* in_sizes, int n_in,
                              void* d_out, int out_size) {
    const float* x     = (const float*)d_in[0];
    const float* lam   = (const float*)d_in[1];
    const float* tau   = (const float*)d_in[2];
    const float* theta = (const float*)d_in[3];
    const float* wx    = (const float*)d_in[4];
    const float* wy    = (const float*)d_in[5];
    float* out = (float*)d_out;

    pre_kernel<<<(Ntot/4 + 255)/256, 256>>>(x);

    dim3 grid(NT2, NT2, Bn);   // 19 x 19 x 4 = 1444 blocks
    for (int i = 0; i < NPAIR; i++)
        iter2_kernel<<<grid, 256>>>(i & 1, i == NPAIR-1, lam, tau, theta, wx, wy);

    avg_kernel<<<(Ntot/4 + 255)/256, 256>>>(out);
}

// round 17
// speedup vs baseline: 1.1174x; 1.0971x over previous
#include <cuda_runtime.h>

#define Bn 4
#define Hh 512
#define Ww 512
#define HW (Hh*Ww)
#define Ntot (Bn*HW)
#define EPSf 1e-8f
#define T2 28          // owned interior per block (middle launches)
#define T2L 27         // owned interior on the last (avg-fused) launch
#define NT2 19         // 19*28=532 and 19*27=513 both cover 512
#define SPU 33         // s_u pitch (float2)
#define SPP 33         // s_pa/s_pb pitch (float2)

// State in vector-packed device globals (no runtime alloc).
// pa=(p1x,p2x) read at w+-1 (horizontal), pb=(p1y,p2y) read at h+-1 (vertical).
__device__ float4 g_cfg[Ntot];        // (rho_c, gx, gy, pad)
__device__ float2 g_u2[2][Ntot];
__device__ float2 g_pa[2][Ntot];
__device__ float2 g_pb[2][Ntot];

// cfg = (I1-I0, K_GRAD_x*I1, K_GRAD_y*I1), zero padding. No state init needed:
// iter2_first never reads state (u=p=0 analytically) and buf0 is written
// (middle launch i=1) before it is ever read (i=2).
__global__ void pre_kernel(const float* __restrict__ x) {
    int i = blockIdx.x*blockDim.x + threadIdx.x;
    if (i >= Ntot/4) return;
    int b   = i >> 16;               // HW/4 = 65536
    int hw4 = i & 65535;
    int h   = hw4 >> 7;              // 128 groups per row
    int wg  = (hw4 & 127) << 2;      // first col of the 4-pixel group

    const float* I0 = x + (size_t)b*2*HW;
    const float* I1 = I0 + HW;

    float r[3][6];
    #pragma unroll
    for (int d = 0; d < 3; d++) {
        int hh = h + d - 1;
        if ((unsigned)hh < Hh) {
            const float* row = I1 + hh*Ww;
            float4 m = *reinterpret_cast<const float4*>(row + wg);
            r[d][0] = (wg > 0) ? row[wg-1] : 0.f;
            r[d][1] = m.x; r[d][2] = m.y; r[d][3] = m.z; r[d][4] = m.w;
            r[d][5] = (wg+4 < Ww) ? row[wg+4] : 0.f;
        } else {
            #pragma unroll
            for (int j = 0; j < 6; j++) r[d][j] = 0.f;
        }
    }
    float4 c0 = *reinterpret_cast<const float4*>(I0 + h*Ww + wg);
    float i0c[4] = {c0.x, c0.y, c0.z, c0.w};

    int pidx = b*HW + h*Ww + wg;
    #pragma unroll
    for (int k = 0; k < 4; k++) {
        float gx = (-r[0][k] + r[0][k+2] - 2.f*r[1][k] + 2.f*r[1][k+2]
                    - r[2][k] + r[2][k+2]) * (1.f/6.f);
        float gy = (-r[0][k] - 2.f*r[0][k+1] - r[0][k+2]
                    + r[2][k] + 2.f*r[2][k+1] + r[2][k+2]) * (1.f/6.f);
        g_cfg[pidx+k] = make_float4(r[1][k+1] - i0c[k], gx, gy, 0.f);
    }
}

// Shared math: u-update delta given rho (v = u - delta)
__device__ __forceinline__ void tvl1_delta(float rho, float gx, float gy,
                                           float ng, float tl,
                                           float& d0, float& d1) {
    float th = tl * ng;
    if (fabsf(rho) < th) {
        float inv = 1.0f / ng;
        d0 = rho*gx*inv; d1 = rho*gy*inv;
    } else {
        float s = (rho > 0.f) ? 1.f : ((rho < 0.f) ? -1.f : 0.f);
        d0 = tl*gx*s; d1 = tl*gy*s;
    }
}

// ============ FIRST launch: iterations 1+2 from the zero state ============
// Phase A needs no u/p loads (u=p=0): u(1) = -delta(rho_c). Phase B: p_in=0.
// Phases C/D identical to the common kernel. Writes buf 1 (src=0 semantics).
__global__ __launch_bounds__(256) void iter2_first_kernel(
    const float* __restrict__ lam_p, const float* __restrict__ tau_p,
    const float* __restrict__ theta_p,
    const float* __restrict__ wx, const float* __restrict__ wy)
{
    const float theta = theta_p[0];
    const float tl = theta * lam_p[0];
    const float rr = tau_p[0] / theta;
    const float wx0 = wx[0], wx1 = wx[1], wx2 = wx[2];
    const float wy0 = wy[0], wy1 = wy[1], wy2 = wy[2];

    float2* __restrict__ u_out  = g_u2[1];
    float2* __restrict__ pa_out = g_pa[1];
    float2* __restrict__ pb_out = g_pb[1];

    const int lc = threadIdx.x & 31;
    const int ty = threadIdx.x >> 5;
    const int b  = blockIdx.z;
    const int gh0 = blockIdx.y * T2 - 1;
    const int gw0 = blockIdx.x * T2 - 1;
    const int gw  = gw0 + lc;
    const int base = b * HW;
    const bool wok = (unsigned)gw < Ww;

    __shared__ float2 s_u [32*SPU];
    __shared__ float2 s_pa[31*SPP];
    __shared__ float2 s_pb[31*SPP];

    // ---- Phase A: u(1) = -delta(rho_c); no state loads ----
    #pragma unroll
    for (int i = 0; i < 4; i++) {
        int lr = ty + i*8;
        int gh = gh0 + lr;
        float2 res = make_float2(0.f, 0.f);
        if ((unsigned)gh < Hh && wok) {
            float4 cfg = g_cfg[base + gh*Ww + gw];
            float gx = cfg.y, gy = cfg.z;
            float ng = gx*gx + gy*gy + EPSf;
            float d0, d1;
            tvl1_delta(cfg.x, gx, gy, ng, tl, d0, d1);
            res.x = -d0;
            res.y = -d1;
        }
        s_u[lr*SPU + lc] = res;
    }
    __syncthreads();

    // ---- Phase B: p(1) from p=0 ----
    #pragma unroll
    for (int i = 0; i < 4; i++) {
        int lr = ty + i*8;
        if (lr < 31 && lc < 31) {
            int gh = gh0 + lr;
            float2 ra = make_float2(0.f, 0.f), rb = make_float2(0.f, 0.f);
            if ((unsigned)gh < Hh && wok) {
                float2 c   = s_u[lr*SPU + lc];
                float2 rgt = s_u[lr*SPU + lc + 1];
                float2 dwn = s_u[(lr+1)*SPU + lc];
                float gx0 = rgt.x - c.x, gy0 = dwn.x - c.x;
                float gx1 = rgt.y - c.y, gy1 = dwn.y - c.y;
                float i1 = rr / (1.f + rr*(fabsf(gx0) + fabsf(gy0)));
                float i2 = rr / (1.f + rr*(fabsf(gx1) + fabsf(gy1)));
                ra = make_float2(gx0*i1, gx1*i2);
                rb = make_float2(gy0*i1, gy1*i2);
            }
            s_pa[lr*SPP + lc] = ra;
            s_pb[lr*SPP + lc] = rb;
        }
    }
    __syncthreads();

    // ---- Phase C: u(2) on [1,30)^2 ----
    #pragma unroll
    for (int i = 0; i < 4; i++) {
        int lr = ty + i*8;
        if (lr >= 1 && lr < 30 && lc >= 1 && lc < 30) {
            int gh = gh0 + lr;
            float2 res = make_float2(0.f, 0.f);
            if ((unsigned)gh < Hh && wok) {
                float4 cfg = g_cfg[base + gh*Ww + gw];
                float2 u  = s_u[lr*SPU + lc];
                float2 pa = s_pa[lr*SPP + lc];
                float2 pb = s_pb[lr*SPP + lc];
                float2 pl = s_pa[lr*SPP + lc - 1];
                float2 pr = s_pa[lr*SPP + lc + 1];
                float2 pu = s_pb[(lr-1)*SPP + lc];
                float2 pd = s_pb[(lr+1)*SPP + lc];
                float gx = cfg.y, gy = cfg.z;
                float ng = gx*gx + gy*gy + EPSf;
                float d0, d1;
                tvl1_delta(cfg.x + gx*u.x + gy*u.y, gx, gy, ng, tl, d0, d1);
                float div1 = wx0*pl.x + wx1*pa.x + wx2*pr.x + wy0*pu.x + wy1*pb.x + wy2*pd.x;
                float div2 = wx0*pl.y + wx1*pa.y + wx2*pr.y + wy0*pu.y + wy1*pb.y + wy2*pd.y;
                res.x = (u.x - d0) + theta*div1;
                res.y = (u.y - d1) + theta*div2;
            }
            s_u[lr*SPU + lc] = res;
        }
    }
    __syncthreads();

    // ---- Phase D: p(2) + state writes on the 28x28 owned interior ----
    #pragma unroll
    for (int i = 0; i < 4; i++) {
        int lr = ty + i*8;
        if (lr >= 1 && lr < 29 && lc >= 1 && lc < 29) {
            int gh = gh0 + lr;
            if ((unsigned)gh < Hh && wok) {
                int idx = base + gh*Ww + gw;
                float2 c = s_u[lr*SPU + lc];
                u_out[idx] = c;
                float2 pa  = s_pa[lr*SPP + lc];
                float2 pb  = s_pb[lr*SPP + lc];
                float2 rgt = s_u[lr*SPU + lc + 1];
                float2 dwn = s_u[(lr+1)*SPU + lc];
                float gx0 = rgt.x - c.x, gy0 = dwn.x - c.x;
                float gx1 = rgt.y - c.y, gy1 = dwn.y - c.y;
                float i1 = 1.f / (1.f + rr*(fabsf(gx0) + fabsf(gy0)));
                float i2 = 1.f / (1.f + rr*(fabsf(gx1) + fabsf(gy1)));
                pa_out[idx] = make_float2((pa.x + rr*gx0)*i1, (pa.y + rr*gx1)*i2);
                pb_out[idx] = make_float2((pb.x + rr*gy0)*i1, (pb.y + rr*gy1)*i2);
            }
        }
    }
}

// ============ MIDDLE launches: byte-exact R5 pair kernel ============
__global__ __launch_bounds__(256) void iter2_kernel(int src,
    const float* __restrict__ lam_p, const float* __restrict__ tau_p,
    const float* __restrict__ theta_p,
    const float* __restrict__ wx, const float* __restrict__ wy)
{
    const float theta = theta_p[0];
    const float tl = theta * lam_p[0];
    const float rr = tau_p[0] / theta;
    const float wx0 = wx[0], wx1 = wx[1], wx2 = wx[2];
    const float wy0 = wy[0], wy1 = wy[1], wy2 = wy[2];

    const float2* __restrict__ u_in  = g_u2[src];
    const float2* __restrict__ pa_in = g_pa[src];
    const float2* __restrict__ pb_in = g_pb[src];
    float2* __restrict__ u_out  = g_u2[src^1];
    float2* __restrict__ pa_out = g_pa[src^1];
    float2* __restrict__ pb_out = g_pb[src^1];

    const int lc = threadIdx.x & 31;
    const int ty = threadIdx.x >> 5;
    const int b  = blockIdx.z;
    const int gh0 = blockIdx.y * T2 - 1;
    const int gw0 = blockIdx.x * T2 - 1;
    const int gw  = gw0 + lc;
    const int base = b * HW;
    const bool wok = (unsigned)gw < Ww;

    __shared__ float2 s_u [32*SPU];
    __shared__ float2 s_pa[31*SPP];
    __shared__ float2 s_pb[31*SPP];

    // ---- Phase A: u(1) on full 32x32 region ----
    #pragma unroll
    for (int i = 0; i < 4; i++) {
        int lr = ty + i*8;
        int gh = gh0 + lr;
        float2 res = make_float2(0.f, 0.f);
        if ((unsigned)gh < Hh && wok) {
            int idx = base + gh*Ww + gw;
            float4 cfg = g_cfg[idx];
            float2 u  = u_in[idx];
            float2 pa = pa_in[idx];
            float2 pb = pb_in[idx];
            float2 z2 = make_float2(0.f, 0.f);
            float2 pl = (gw > 0)    ? pa_in[idx-1]  : z2;
            float2 pr = (gw < Ww-1) ? pa_in[idx+1]  : z2;
            float2 pu = (gh > 0)    ? pb_in[idx-Ww] : z2;
            float2 pd = (gh < Hh-1) ? pb_in[idx+Ww] : z2;
            float gx = cfg.y, gy = cfg.z;
            float ng = gx*gx + gy*gy + EPSf;
            float d0, d1;
            tvl1_delta(cfg.x + gx*u.x + gy*u.y, gx, gy, ng, tl, d0, d1);
            float div1 = wx0*pl.x + wx1*pa.x + wx2*pr.x + wy0*pu.x + wy1*pb.x + wy2*pd.x;
            float div2 = wx0*pl.y + wx1*pa.y + wx2*pr.y + wy0*pu.y + wy1*pb.y + wy2*pd.y;
            res.x = (u.x - d0) + theta*div1;
            res.y = (u.y - d1) + theta*div2;
        }
        s_u[lr*SPU + lc] = res;
    }
    __syncthreads();

    // ---- Phase B: p(1) on 31x31 region ----
    #pragma unroll
    for (int i = 0; i < 4; i++) {
        int lr = ty + i*8;
        if (lr < 31 && lc < 31) {
            int gh = gh0 + lr;
            float2 ra = make_float2(0.f, 0.f), rb = make_float2(0.f, 0.f);
            if ((unsigned)gh < Hh && wok) {
                int idx = base + gh*Ww + gw;
                float2 pa = pa_in[idx];
                float2 pb = pb_in[idx];
                float2 c   = s_u[lr*SPU + lc];
                float2 rgt = s_u[lr*SPU + lc + 1];
                float2 dwn = s_u[(lr+1)*SPU + lc];
                float gx0 = rgt.x - c.x, gy0 = dwn.x - c.x;
                float gx1 = rgt.y - c.y, gy1 = dwn.y - c.y;
                float i1 = 1.f / (1.f + rr*(fabsf(gx0) + fabsf(gy0)));
                float i2 = 1.f / (1.f + rr*(fabsf(gx1) + fabsf(gy1)));
                ra = make_float2((pa.x + rr*gx0)*i1, (pa.y + rr*gx1)*i2);
                rb = make_float2((pb.x + rr*gy0)*i1, (pb.y + rr*gy1)*i2);
            }
            s_pa[lr*SPP + lc] = ra;
            s_pb[lr*SPP + lc] = rb;
        }
    }
    __syncthreads();

    // ---- Phase C: u(2) on [1,30)^2 ----
    #pragma unroll
    for (int i = 0; i < 4; i++) {
        int lr = ty + i*8;
        if (lr >= 1 && lr < 30 && lc >= 1 && lc < 30) {
            int gh = gh0 + lr;
            float2 res = make_float2(0.f, 0.f);
            if ((unsigned)gh < Hh && wok) {
                float4 cfg = g_cfg[base + gh*Ww + gw];
                float2 u  = s_u[lr*SPU + lc];
                float2 pa = s_pa[lr*SPP + lc];
                float2 pb = s_pb[lr*SPP + lc];
                float2 pl = s_pa[lr*SPP + lc - 1];
                float2 pr = s_pa[lr*SPP + lc + 1];
                float2 pu = s_pb[(lr-1)*SPP + lc];
                float2 pd = s_pb[(lr+1)*SPP + lc];
                float gx = cfg.y, gy = cfg.z;
                float ng = gx*gx + gy*gy + EPSf;
                float d0, d1;
                tvl1_delta(cfg.x + gx*u.x + gy*u.y, gx, gy, ng, tl, d0, d1);
                float div1 = wx0*pl.x + wx1*pa.x + wx2*pr.x + wy0*pu.x + wy1*pb.x + wy2*pd.x;
                float div2 = wx0*pl.y + wx1*pa.y + wx2*pr.y + wy0*pu.y + wy1*pb.y + wy2*pd.y;
                res.x = (u.x - d0) + theta*div1;
                res.y = (u.y - d1) + theta*div2;
            }
            s_u[lr*SPU + lc] = res;
        }
    }
    __syncthreads();

    // ---- Phase D: p(2) + state writes on the 28x28 owned interior ----
    #pragma unroll
    for (int i = 0; i < 4; i++) {
        int lr = ty + i*8;
        if (lr >= 1 && lr < 29 && lc >= 1 && lc < 29) {
            int gh = gh0 + lr;
            if ((unsigned)gh < Hh && wok) {
                int idx = base + gh*Ww + gw;
                float2 c = s_u[lr*SPU + lc];
                u_out[idx] = c;
                float2 pa  = s_pa[lr*SPP + lc];
                float2 pb  = s_pb[lr*SPP + lc];
                float2 rgt = s_u[lr*SPU + lc + 1];
                float2 dwn = s_u[(lr+1)*SPU + lc];
                float gx0 = rgt.x - c.x, gy0 = dwn.x - c.x;
                float gx1 = rgt.y - c.y, gy1 = dwn.y - c.y;
                float i1 = 1.f / (1.f + rr*(fabsf(gx0) + fabsf(gy0)));
                float i2 = 1.f / (1.f + rr*(fabsf(gx1) + fabsf(gy1)));
                pa_out[idx] = make_float2((pa.x + rr*gx0)*i1, (pa.y + rr*gx1)*i2);
                pb_out[idx] = make_float2((pb.x + rr*gy0)*i1, (pb.y + rr*gy1)*i2);
            }
        }
    }
}

// ============ LAST launch: iterations 19+20 + fused AvgPool ============
// Phases A-C as the common kernel but with 27x27 owned tiles (origin -2);
// phase D = AvgPool3x3(u(2))/9 from SMEM straight to out. No state writes.
// Phase C zeroes out-of-image points, so the 9-tap sum sees exact zero-pad.
__global__ __launch_bounds__(256) void iter2_last_kernel(int src,
    float* __restrict__ out,
    const float* __restrict__ lam_p, const float* __restrict__ tau_p,
    const float* __restrict__ theta_p,
    const float* __restrict__ wx, const float* __restrict__ wy)
{
    const float theta = theta_p[0];
    const float tl = theta * lam_p[0];
    const float rr = tau_p[0] / theta;
    const float wx0 = wx[0], wx1 = wx[1], wx2 = wx[2];
    const float wy0 = wy[0], wy1 = wy[1], wy2 = wy[2];

    const float2* __restrict__ u_in  = g_u2[src];
    const float2* __restrict__ pa_in = g_pa[src];
    const float2* __restrict__ pb_in = g_pb[src];

    const int lc = threadIdx.x & 31;
    const int ty = threadIdx.x >> 5;
    const int b  = blockIdx.z;
    const int gh0 = blockIdx.y * T2L - 2;
    const int gw0 = blockIdx.x * T2L - 2;
    const int gw  = gw0 + lc;
    const int base = b * HW;
    const bool wok = (unsigned)gw < Ww;

    __shared__ float2 s_u [32*SPU];
    __shared__ float2 s_pa[31*SPP];
    __shared__ float2 s_pb[31*SPP];

    // ---- Phase A ----
    #pragma unroll
    for (int i = 0; i < 4; i++) {
        int lr = ty + i*8;
        int gh = gh0 + lr;
        float2 res = make_float2(0.f, 0.f);
        if ((unsigned)gh < Hh && wok) {
            int idx = base + gh*Ww + gw;
            float4 cfg = g_cfg[idx];
            float2 u  = u_in[idx];
            float2 pa = pa_in[idx];
            float2 pb = pb_in[idx];
            float2 z2 = make_float2(0.f, 0.f);
            float2 pl = (gw > 0)    ? pa_in[idx-1]  : z2;
            float2 pr = (gw < Ww-1) ? pa_in[idx+1]  : z2;
            float2 pu = (gh > 0)    ? pb_in[idx-Ww] : z2;
            float2 pd = (gh < Hh-1) ? pb_in[idx+Ww] : z2;
            float gx = cfg.y, gy = cfg.z;
            float ng = gx*gx + gy*gy + EPSf;
            float d0, d1;
            tvl1_delta(cfg.x + gx*u.x + gy*u.y, gx, gy, ng, tl, d0, d1);
            float div1 = wx0*pl.x + wx1*pa.x + wx2*pr.x + wy0*pu.x + wy1*pb.x + wy2*pd.x;
            float div2 = wx0*pl.y + wx1*pa.y + wx2*pr.y + wy0*pu.y + wy1*pb.y + wy2*pd.y;
            res.x = (u.x - d0) + theta*div1;
            res.y = (u.y - d1) + theta*div2;
        }
        s_u[lr*SPU + lc] = res;
    }
    __syncthreads();

    // ---- Phase B ----
    #pragma unroll
    for (int i = 0; i < 4; i++) {
        int lr = ty + i*8;
        if (lr < 31 && lc < 31) {
            int gh = gh0 + lr;
            float2 ra = make_float2(0.f, 0.f), rb = make_float2(0.f, 0.f);
            if ((unsigned)gh < Hh && wok) {
                int idx = base + gh*Ww + gw;
                float2 pa = pa_in[idx];
                float2 pb = pb_in[idx];
                float2 c   = s_u[lr*SPU + lc];
                float2 rgt = s_u[lr*SPU + lc + 1];
                float2 dwn = s_u[(lr+1)*SPU + lc];
                float gx0 = rgt.x - c.x, gy0 = dwn.x - c.x;
                float gx1 = rgt.y - c.y, gy1 = dwn.y - c.y;
                float i1 = 1.f / (1.f + rr*(fabsf(gx0) + fabsf(gy0)));
                float i2 = 1.f / (1.f + rr*(fabsf(gx1) + fabsf(gy1)));
                ra = make_float2((pa.x + rr*gx0)*i1, (pa.y + rr*gx1)*i2);
                rb = make_float2((pb.x + rr*gy0)*i1, (pb.y + rr*gy1)*i2);
            }
            s_pa[lr*SPP + lc] = ra;
            s_pb[lr*SPP + lc] = rb;
        }
    }
    __syncthreads();

    // ---- Phase C ----
    #pragma unroll
    for (int i = 0; i < 4; i++) {
        int lr = ty + i*8;
        if (lr >= 1 && lr < 30 && lc >= 1 && lc < 30) {
            int gh = gh0 + lr;
            float2 res = make_float2(0.f, 0.f);
            if ((unsigned)gh < Hh && wok) {
                float4 cfg = g_cfg[base + gh*Ww + gw];
                float2 u  = s_u[lr*SPU + lc];
                float2 pa = s_pa[lr*SPP + lc];
                float2 pb = s_pb[lr*SPP + lc];
                float2 pl = s_pa[lr*SPP + lc - 1];
                float2 pr = s_pa[lr*SPP + lc + 1];
                float2 pu = s_pb[(lr-1)*SPP + lc];
                float2 pd = s_pb[(lr+1)*SPP + lc];
                float gx = cfg.y, gy = cfg.z;
                float ng = gx*gx + gy*gy + EPSf;
                float d0, d1;
                tvl1_delta(cfg.x + gx*u.x + gy*u.y, gx, gy, ng, tl, d0, d1);
                float div1 = wx0*pl.x + wx1*pa.x + wx2*pr.x + wy0*pu.x + wy1*pb.x + wy2*pd.x;
                float div2 = wx0*pl.y + wx1*pa.y + wx2*pr.y + wy0*pu.y + wy1*pb.y + wy2*pd.y;
                res.x = (u.x - d0) + theta*div1;
                res.y = (u.y - d1) + theta*div2;
            }
            s_u[lr*SPU + lc] = res;
        }
    }
    __syncthreads();

    // ---- Phase D: AvgPool3x3(u(2))/9 on [2,29)^2, direct to out ----
    #pragma unroll
    for (int i = 0; i < 4; i++) {
        int lr = ty + i*8;
        if (lr >= 2 && lr < 29 && lc >= 2 && lc < 29) {
            int gh = gh0 + lr;
            if ((unsigned)gh < Hh && wok) {
                float sx = 0.f, sy = 0.f;
                #pragma unroll
                for (int dr = -1; dr <= 1; dr++) {
                    #pragma unroll
                    for (int dc = -1; dc <= 1; dc++) {
                        float2 v = s_u[(lr+dr)*SPU + (lc+dc)];
                        sx += v.x; sy += v.y;
                    }
                }
                int o = b*2*HW + gh*Ww + gw;
                out[o]      = sx * (1.f/9.f);
                out[o + HW] = sy * (1.f/9.f);
            }
        }
    }
}

extern "C" void kernel_launch(void* const* d_in, const int* in_sizes, int n_in,
                              void* d_out, int out_size) {
    const float* x     = (const float*)d_in[0];
    const float* lam   = (const float*)d_in[1];
    const float* tau   = (const float*)d_in[2];
    const float* theta = (const float*)d_in[3];
    const float* wx    = (const float*)d_in[4];
    const float* wy    = (const float*)d_in[5];
    float* out = (float*)d_out;

    pre_kernel<<<(Ntot/4 + 255)/256, 256>>>(x);

    dim3 grid(NT2, NT2, Bn);   // 19 x 19 x 4 = 1444 blocks
    // iterations 1-2 from the zero state -> buf 1
    iter2_first_kernel<<<grid, 256>>>(lam, tau, theta, wx, wy);
    // iterations 3-18: 8 middle pairs, src alternates 1,0,1,0,1,0,1,0 -> buf 1
    for (int i = 1; i <= 8; i++)
        iter2_kernel<<<grid, 256>>>(i & 1, lam, tau, theta, wx, wy);
    // iterations 19-20 + fused AvgPool -> out
    iter2_last_kernel<<<grid, 256>>>(1, out, lam, tau, theta, wx, wy);
}